// round 3
// baseline (speedup 1.0000x reference)
#include <cuda_runtime.h>
#include <math_constants.h>

// ---------------- problem constants ----------------
#define BATCH 4
#define HW    16384          // 128*128
#define THR   0.1f
#define TS    2048           // shared column tile == column chunk
#define RPT   4              // rows per thread in dist kernel
#define DBLK  512            // threads per dist block  -> 2048 rows/block
#define ROWCHUNK (DBLK*RPT)  // 2048
#define NSLICE 8             // compact slices
#define FSLICE 16            // final slices

// ---------------- device scratch (no allocs allowed; zero-initialized) ------
__device__ float g_px[2][BATCH][HW];
__device__ float g_py[2][BATCH][HW];
__device__ float g_pn[2][BATCH][HW];
__device__ int   g_cnt[2][BATCH];                  // statically 0; k_out re-zeros
__device__ unsigned int g_minbuf[8][HW];           // [dir*4+b][row], ordered-uint
__device__ float g_part[8][FSLICE];                // partial sums

// ---------------- helpers ----------------
__device__ __forceinline__ unsigned fp_ord(float f) {
    unsigned u = __float_as_uint(f);
    return (u & 0x80000000u) ? ~u : (u | 0x80000000u);
}
__device__ __forceinline__ float fp_unord(unsigned u) {
    u = (u & 0x80000000u) ? (u & 0x7fffffffu) : ~u;
    return __uint_as_float(u);
}
__device__ __forceinline__ unsigned long long pack2(float lo, float hi) {
    unsigned long long r;
    asm("mov.b64 %0, {%1,%2};" : "=l"(r) : "f"(lo), "f"(hi));
    return r;
}
__device__ __forceinline__ void unpack2(unsigned long long p, float& lo, float& hi) {
    asm("mov.b64 {%0,%1}, %2;" : "=f"(lo), "=f"(hi) : "l"(p));
}
__device__ __forceinline__ unsigned long long fma2(unsigned long long a,
                                                   unsigned long long b,
                                                   unsigned long long c) {
    unsigned long long d;
    asm("fma.rn.f32x2 %0, %1, %2, %3;" : "=l"(d) : "l"(a), "l"(b), "l"(c));
    return d;
}

// ---------------- kernel 1: compaction + minbuf init ----------------
// grid (NSLICE, 8 set*4+b), 256 threads; order within compacted array is free
__global__ void k_compact(const float* __restrict__ b1, const float* __restrict__ b2) {
    int bs = blockIdx.y;
    int set = bs >> 2, b = bs & 3;
    const float* src = (set == 0 ? b1 : b2) + b * HW;
    int begin = blockIdx.x * (HW / NSLICE);        // 2048-element slice

    // init min buffer slice (z == bs: rows of dir==set)
    {
        uint4* mb = (uint4*)&g_minbuf[bs][begin];
        uint4 v = make_uint4(0xFFFFFFFFu, 0xFFFFFFFFu, 0xFFFFFFFFu, 0xFFFFFFFFu);
        for (int i = threadIdx.x; i < (HW / NSLICE) / 4; i += 256) mb[i] = v;
    }

    int lane = threadIdx.x & 31;
    for (int k = 0; k < (HW / NSLICE) / 256; k++) { // uniform trip count: ballot safe
        int i = begin + k * 256 + threadIdx.x;
        float v = src[i];
        float w = v - THR;
        bool act = (w > 0.0f);
        unsigned mask = __ballot_sync(0xffffffffu, act);
        int c = __popc(mask);
        int base = 0;
        if (lane == 0 && c) base = atomicAdd(&g_cnt[set][b], c);
        base = __shfl_sync(0xffffffffu, base, 0);
        if (act) {
            int pos = base + __popc(mask & ((1u << lane) - 1u));
            float y = (float)(i >> 7);
            float x = (float)(i & 127);
            float px = y * w, py = x * w;
            g_px[set][b][pos] = px;
            g_py[set][b][pos] = py;
            g_pn[set][b][pos] = fmaf(px, px, py * py);
        }
    }
}

// ---------------- kernel 2: pairwise min (GEMM-form) ----------------
// grid (8, 8, 8): x=row chunk (2048 rows), y=col chunk (2048 cols), z=dir*4+b
__global__ void __launch_bounds__(DBLK) k_dist() {
    int z = blockIdx.z;
    int dir = z >> 2, b = z & 3;
    int n1 = g_cnt[dir][b];          // rows come from set==dir
    int n2 = g_cnt[dir ^ 1][b];      // columns from the other set

    int rowBase = blockIdx.x * ROWCHUNK;
    int colBase = blockIdx.y * TS;
    if (rowBase >= n1 || colBase >= n2) return;   // uniform per block

    __shared__ __align__(16) float sqx[TS];
    __shared__ __align__(16) float sqy[TS];
    __shared__ __align__(16) float sqn[TS];

    const float* qx = g_px[dir ^ 1][b];
    const float* qy = g_py[dir ^ 1][b];
    const float* qn = g_pn[dir ^ 1][b];

    int t = threadIdx.x;
    const float FINF = CUDART_INF_F;

    // unconditional vector tile load; force qn=INF beyond n2 so padded columns
    // self-exclude (stale qx/qy are finite -> chain stays +INF, never NaN/-INF)
    {
        float4 vx = ((const float4*)(qx + colBase))[t];
        float4 vy = ((const float4*)(qy + colBase))[t];
        float4 vn = ((const float4*)(qn + colBase))[t];
        int cbase = colBase + t * 4;
        vn.x = (cbase + 0 < n2) ? vn.x : FINF;
        vn.y = (cbase + 1 < n2) ? vn.y : FINF;
        vn.z = (cbase + 2 < n2) ? vn.z : FINF;
        vn.w = (cbase + 3 < n2) ? vn.w : FINF;
        ((float4*)sqx)[t] = vx;
        ((float4*)sqy)[t] = vy;
        ((float4*)sqn)[t] = vn;
    }

    unsigned long long a2[RPT], b2[RPT];
    float mnL[RPT], mnH[RPT];
#pragma unroll
    for (int r = 0; r < RPT; r++) {
        int row = rowBase + t + r * DBLK;
        float px = 0.0f, py = 0.0f;
        if (row < n1) { px = g_px[dir][b][row]; py = g_py[dir][b][row]; }
        float a = -2.0f * px, bb = -2.0f * py;
        a2[r] = pack2(a, a);
        b2[r] = pack2(bb, bb);
        mnL[r] = FINF;
        mnH[r] = FINF;
    }

    __syncthreads();

#pragma unroll 2
    for (int j = 0; j < TS; j += 4) {
        ulonglong2 X = *(const ulonglong2*)&sqx[j];
        ulonglong2 Y = *(const ulonglong2*)&sqy[j];
        ulonglong2 N = *(const ulonglong2*)&sqn[j];
#pragma unroll
        for (int r = 0; r < RPT; r++) {
            unsigned long long v01 = fma2(a2[r], X.x, fma2(b2[r], Y.x, N.x));
            unsigned long long v23 = fma2(a2[r], X.y, fma2(b2[r], Y.y, N.y));
            float l0, h0, l1, h1;
            unpack2(v01, l0, h0);
            unpack2(v23, l1, h1);
            mnL[r] = fminf(mnL[r], l0);
            mnH[r] = fminf(mnH[r], h0);
            mnL[r] = fminf(mnL[r], l1);
            mnH[r] = fminf(mnH[r], h1);
        }
    }

#pragma unroll
    for (int r = 0; r < RPT; r++) {
        int row = rowBase + t + r * DBLK;
        if (row < n1) atomicMin(&g_minbuf[z][row], fp_ord(fminf(mnL[r], mnH[r])));
    }
}

// ---------------- kernel 3: per-direction partial sums (atomic-free) --------
// grid (FSLICE, 8 z), 256 threads
__global__ void k_final() {
    int z = blockIdx.y;
    int dir = z >> 2, b = z & 3;
    int n1 = g_cnt[dir][b];
    const float4* pn = (const float4*)g_pn[dir][b];
    const uint4*  mb = (const uint4*)g_minbuf[z];

    int begin4 = blockIdx.x * (HW / FSLICE / 4);    // in float4 units (256 per slice)
    float s = 0.0f;
    {
        int i4 = begin4 + threadIdx.x;              // one float4 per thread
        float4 p = pn[i4];
        uint4  m = mb[i4];
        int row = i4 * 4;
        if (row + 0 < n1) s += sqrtf(fmaxf(p.x + fp_unord(m.x), 1e-12f));
        if (row + 1 < n1) s += sqrtf(fmaxf(p.y + fp_unord(m.y), 1e-12f));
        if (row + 2 < n1) s += sqrtf(fmaxf(p.z + fp_unord(m.z), 1e-12f));
        if (row + 3 < n1) s += sqrtf(fmaxf(p.w + fp_unord(m.w), 1e-12f));
    }
    for (int o = 16; o; o >>= 1) s += __shfl_down_sync(0xffffffffu, s, o);
    __shared__ float ws[8];
    if ((threadIdx.x & 31) == 0) ws[threadIdx.x >> 5] = s;
    __syncthreads();
    if (threadIdx.x < 8) {
        float v = ws[threadIdx.x];
        for (int o = 4; o; o >>= 1) v += __shfl_down_sync(0xffu, v, o);
        if (threadIdx.x == 0) g_part[z][blockIdx.x] = v;
    }
}

// ---------------- kernel 4: combine partials + sentinel + counter reset -----
__global__ void k_out(float* __restrict__ out) {
    __shared__ float zs[8];
    int t = threadIdx.x;                            // 128 threads: 8 z * 16 slices
    int z = t >> 4, sl = t & 15;
    float v = g_part[z][sl];
    for (int o = 8; o; o >>= 1) v += __shfl_down_sync(0xffffffffu, v, o);
    if (sl == 0) zs[z] = v;                         // lane (z*16) is lane 0 or 16
    __syncthreads();
    if (t < BATCH) {
        int b = t;
        int n1 = g_cnt[0][b], n2 = g_cnt[1][b];
        float r = zs[b] / (float)max(n1, 1) + zs[4 + b] / (float)max(n2, 1);
        out[b] = (n1 > 0 && n2 > 0) ? r : 1.0e6f;
    }
    __syncthreads();
    if (t < 8) ((int*)g_cnt)[t] = 0;                // reset for next replay
}

// ---------------- launch ----------------
extern "C" void kernel_launch(void* const* d_in, const int* in_sizes, int n_in,
                              void* d_out, int out_size) {
    const float* b1 = (const float*)d_in[0];
    const float* b2 = (const float*)d_in[1];
    float* out = (float*)d_out;

    {
        dim3 g(NSLICE, 8);
        k_compact<<<g, 256>>>(b1, b2);
    }
    {
        dim3 g(HW / ROWCHUNK, HW / TS, 8);   // (8, 8, 8)
        k_dist<<<g, DBLK>>>();
    }
    {
        dim3 g(FSLICE, 8);
        k_final<<<g, 256>>>();
    }
    k_out<<<1, 128>>>(out);
}

// round 4
// speedup vs baseline: 1.4178x; 1.4178x over previous
#include <cuda_runtime.h>
#include <math_constants.h>

// ---------------- problem constants ----------------
#define BATCH 4
#define HW    16384          // 128*128
#define THR   0.1f
#define TS    2048           // shared column tile == column chunk
#define RPT   4              // rows per thread in dist kernel
#define DBLK  512            // threads per dist block  -> 2048 rows/block
#define ROWCHUNK (DBLK*RPT)  // 2048
#define NSLICE 8             // compact slices
#define FSLICE 16            // final slices

// ---------------- device scratch (no allocs allowed; zero-initialized) ------
__device__ float g_px[2][BATCH][HW];
__device__ float g_py[2][BATCH][HW];
__device__ float g_pn[2][BATCH][HW];
__device__ int   g_cnt[2][BATCH];                  // statically 0; k_out re-zeros
__device__ unsigned int g_minbuf[8][HW];           // [dir*4+b][row], ordered-uint
__device__ float g_part[8][FSLICE];                // partial sums

// ---------------- helpers ----------------
__device__ __forceinline__ unsigned fp_ord(float f) {
    unsigned u = __float_as_uint(f);
    return (u & 0x80000000u) ? ~u : (u | 0x80000000u);
}
__device__ __forceinline__ float fp_unord(unsigned u) {
    u = (u & 0x80000000u) ? (u & 0x7fffffffu) : ~u;
    return __uint_as_float(u);
}
__device__ __forceinline__ unsigned long long pack2(float lo, float hi) {
    unsigned long long r;
    asm("mov.b64 %0, {%1,%2};" : "=l"(r) : "f"(lo), "f"(hi));
    return r;
}
__device__ __forceinline__ void unpack2(unsigned long long p, float& lo, float& hi) {
    asm("mov.b64 {%0,%1}, %2;" : "=f"(lo), "=f"(hi) : "l"(p));
}
__device__ __forceinline__ unsigned long long fma2(unsigned long long a,
                                                   unsigned long long b,
                                                   unsigned long long c) {
    unsigned long long d;
    asm("fma.rn.f32x2 %0, %1, %2, %3;" : "=l"(d) : "l"(a), "l"(b), "l"(c));
    return d;
}

// ---------------- kernel 1: compaction + minbuf init ----------------
// grid (NSLICE, 8 set*4+b), 256 threads; order within compacted array is free
__global__ void k_compact(const float* __restrict__ b1, const float* __restrict__ b2) {
    int bs = blockIdx.y;
    int set = bs >> 2, b = bs & 3;
    const float* src = (set == 0 ? b1 : b2) + b * HW;
    int begin = blockIdx.x * (HW / NSLICE);        // 2048-element slice

    // init min buffer slice (z == bs: rows of dir==set)
    {
        uint4* mb = (uint4*)&g_minbuf[bs][begin];
        uint4 v = make_uint4(0xFFFFFFFFu, 0xFFFFFFFFu, 0xFFFFFFFFu, 0xFFFFFFFFu);
        for (int i = threadIdx.x; i < (HW / NSLICE) / 4; i += 256) mb[i] = v;
    }

    int lane = threadIdx.x & 31;
    for (int k = 0; k < (HW / NSLICE) / 256; k++) { // uniform trip count: ballot safe
        int i = begin + k * 256 + threadIdx.x;
        float v = src[i];
        float w = v - THR;
        bool act = (w > 0.0f);
        unsigned mask = __ballot_sync(0xffffffffu, act);
        int c = __popc(mask);
        int base = 0;
        if (lane == 0 && c) base = atomicAdd(&g_cnt[set][b], c);
        base = __shfl_sync(0xffffffffu, base, 0);
        if (act) {
            int pos = base + __popc(mask & ((1u << lane) - 1u));
            float y = (float)(i >> 7);
            float x = (float)(i & 127);
            float px = y * w, py = x * w;
            g_px[set][b][pos] = px;
            g_py[set][b][pos] = py;
            g_pn[set][b][pos] = fmaf(px, px, py * py);
        }
    }
}

// ---------------- kernel 2: pairwise min (GEMM-form) ----------------
// grid (8, 8, 8): x=row chunk (2048 rows), y=col chunk (2048 cols), z=dir*4+b
__global__ void __launch_bounds__(DBLK) k_dist() {
    int z = blockIdx.z;
    int dir = z >> 2, b = z & 3;
    int n1 = g_cnt[dir][b];          // rows come from set==dir
    int n2 = g_cnt[dir ^ 1][b];      // columns from the other set

    int rowBase = blockIdx.x * ROWCHUNK;
    int colBase = blockIdx.y * TS;
    if (rowBase >= n1 || colBase >= n2) return;   // uniform per block

    __shared__ __align__(16) float sqx[TS];
    __shared__ __align__(16) float sqy[TS];
    __shared__ __align__(16) float sqn[TS];

    const float* qx = g_px[dir ^ 1][b];
    const float* qy = g_py[dir ^ 1][b];
    const float* qn = g_pn[dir ^ 1][b];

    int t = threadIdx.x;
    const float FINF = CUDART_INF_F;

    // unconditional vector tile load; force qn=INF beyond n2 so padded columns
    // self-exclude (stale qx/qy are finite -> chain stays +INF, never NaN/-INF)
    {
        float4 vx = ((const float4*)(qx + colBase))[t];
        float4 vy = ((const float4*)(qy + colBase))[t];
        float4 vn = ((const float4*)(qn + colBase))[t];
        int cbase = colBase + t * 4;
        vn.x = (cbase + 0 < n2) ? vn.x : FINF;
        vn.y = (cbase + 1 < n2) ? vn.y : FINF;
        vn.z = (cbase + 2 < n2) ? vn.z : FINF;
        vn.w = (cbase + 3 < n2) ? vn.w : FINF;
        ((float4*)sqx)[t] = vx;
        ((float4*)sqy)[t] = vy;
        ((float4*)sqn)[t] = vn;
    }

    unsigned long long a2[RPT], b2[RPT];
    float mnL[RPT], mnH[RPT];
#pragma unroll
    for (int r = 0; r < RPT; r++) {
        int row = rowBase + t + r * DBLK;
        float px = 0.0f, py = 0.0f;
        if (row < n1) { px = g_px[dir][b][row]; py = g_py[dir][b][row]; }
        float a = -2.0f * px, bb = -2.0f * py;
        a2[r] = pack2(a, a);
        b2[r] = pack2(bb, bb);
        mnL[r] = FINF;
        mnH[r] = FINF;
    }

    __syncthreads();

#pragma unroll 2
    for (int j = 0; j < TS; j += 4) {
        ulonglong2 X = *(const ulonglong2*)&sqx[j];
        ulonglong2 Y = *(const ulonglong2*)&sqy[j];
        ulonglong2 N = *(const ulonglong2*)&sqn[j];
#pragma unroll
        for (int r = 0; r < RPT; r++) {
            unsigned long long v01 = fma2(a2[r], X.x, fma2(b2[r], Y.x, N.x));
            unsigned long long v23 = fma2(a2[r], X.y, fma2(b2[r], Y.y, N.y));
            float l0, h0, l1, h1;
            unpack2(v01, l0, h0);
            unpack2(v23, l1, h1);
            mnL[r] = fminf(mnL[r], l0);
            mnH[r] = fminf(mnH[r], h0);
            mnL[r] = fminf(mnL[r], l1);
            mnH[r] = fminf(mnH[r], h1);
        }
    }

#pragma unroll
    for (int r = 0; r < RPT; r++) {
        int row = rowBase + t + r * DBLK;
        if (row < n1) atomicMin(&g_minbuf[z][row], fp_ord(fminf(mnL[r], mnH[r])));
    }
}

// ---------------- kernel 3: per-direction partial sums (atomic-free) --------
// grid (FSLICE, 8 z), 256 threads
__global__ void k_final() {
    int z = blockIdx.y;
    int dir = z >> 2, b = z & 3;
    int n1 = g_cnt[dir][b];
    const float4* pn = (const float4*)g_pn[dir][b];
    const uint4*  mb = (const uint4*)g_minbuf[z];

    int begin4 = blockIdx.x * (HW / FSLICE / 4);    // in float4 units (256 per slice)
    float s = 0.0f;
    {
        int i4 = begin4 + threadIdx.x;              // one float4 per thread
        float4 p = pn[i4];
        uint4  m = mb[i4];
        int row = i4 * 4;
        if (row + 0 < n1) s += sqrtf(fmaxf(p.x + fp_unord(m.x), 1e-12f));
        if (row + 1 < n1) s += sqrtf(fmaxf(p.y + fp_unord(m.y), 1e-12f));
        if (row + 2 < n1) s += sqrtf(fmaxf(p.z + fp_unord(m.z), 1e-12f));
        if (row + 3 < n1) s += sqrtf(fmaxf(p.w + fp_unord(m.w), 1e-12f));
    }
    for (int o = 16; o; o >>= 1) s += __shfl_down_sync(0xffffffffu, s, o);
    __shared__ float ws[8];
    if ((threadIdx.x & 31) == 0) ws[threadIdx.x >> 5] = s;
    __syncthreads();
    if (threadIdx.x < 8) {
        float v = ws[threadIdx.x];
        for (int o = 4; o; o >>= 1) v += __shfl_down_sync(0xffu, v, o);
        if (threadIdx.x == 0) g_part[z][blockIdx.x] = v;
    }
}

// ---------------- kernel 4: combine partials + sentinel + counter reset -----
__global__ void k_out(float* __restrict__ out) {
    __shared__ float zs[8];
    int t = threadIdx.x;                            // 128 threads: 8 z * 16 slices
    int z = t >> 4, sl = t & 15;
    float v = g_part[z][sl];
    for (int o = 8; o; o >>= 1) v += __shfl_down_sync(0xffffffffu, v, o);
    if (sl == 0) zs[z] = v;                         // lane (z*16) is lane 0 or 16
    __syncthreads();
    if (t < BATCH) {
        int b = t;
        int n1 = g_cnt[0][b], n2 = g_cnt[1][b];
        float r = zs[b] / (float)max(n1, 1) + zs[4 + b] / (float)max(n2, 1);
        out[b] = (n1 > 0 && n2 > 0) ? r : 1.0e6f;
    }
    __syncthreads();
    if (t < 8) ((int*)g_cnt)[t] = 0;                // reset for next replay
}

// ---------------- launch ----------------
extern "C" void kernel_launch(void* const* d_in, const int* in_sizes, int n_in,
                              void* d_out, int out_size) {
    const float* b1 = (const float*)d_in[0];
    const float* b2 = (const float*)d_in[1];
    float* out = (float*)d_out;

    {
        dim3 g(NSLICE, 8);
        k_compact<<<g, 256>>>(b1, b2);
    }
    {
        dim3 g(HW / ROWCHUNK, HW / TS, 8);   // (8, 8, 8)
        k_dist<<<g, DBLK>>>();
    }
    {
        dim3 g(FSLICE, 8);
        k_final<<<g, 256>>>();
    }
    k_out<<<1, 128>>>(out);
}